// round 16
// baseline (speedup 1.0000x reference)
#include <cuda_runtime.h>
#include <cuda_fp16.h>
#include <cstdint>
#include <cstddef>

#define N_DIM     512
#define BATCH_DIM 16384
#define NROUND    511
#define NPAIR     256
#define SEG0_END  256               // seg0 = rounds [0,256), seg1 = [256,511)
#define NPAIRROWS 4                 // float2 row-pairs per build block (= 8 rows)

// ---------------- scratch (static device globals; no runtime allocation) ----------------
__device__ __align__(16) uint32_t g_sched[NROUND * NPAIR];   // packed (i | j<<16), oriented
__device__ __align__(16) float2   g_cs  [NROUND * NPAIR];    // matching (cos, sin')
__device__ __align__(16) __half   g_V0h [N_DIM * N_DIM];     // V0, fp16, (m,k) K-major
__device__ __align__(16) __half   g_V1Th[N_DIM * N_DIM];     // V1^T, fp16: [n*512+k] = V1[k][n]
__device__ __align__(16) __half   g_Uh  [N_DIM * N_DIM];     // U = V0*V1, fp16 row-major
__device__ __align__(16) __half   g_xh[(size_t)BATCH_DIM * N_DIM];

// ---------------- helpers ----------------
__device__ __forceinline__ uint32_t smem_u32(const void* p) {
    uint32_t a;
    asm("{ .reg .u64 t; cvta.to.shared.u64 t, %1; cvt.u32.u64 %0, t; }" : "=r"(a) : "l"(p));
    return a;
}

__device__ __forceinline__ void cp_async16(uint32_t s, const void* g) {
    asm volatile("cp.async.cg.shared.global [%0], [%1], 16;" :: "r"(s), "l"(g) : "memory");
}

__device__ __forceinline__ void ldm_x4(uint32_t* r, uint32_t addr) {
    asm volatile("ldmatrix.sync.aligned.m8n8.x4.shared.b16 {%0,%1,%2,%3}, [%4];"
                 : "=r"(r[0]), "=r"(r[1]), "=r"(r[2]), "=r"(r[3]) : "r"(addr));
}

__device__ __forceinline__ void mma16816(float* d, const uint32_t* a, uint32_t b0, uint32_t b1) {
    asm volatile(
        "mma.sync.aligned.m16n8k16.row.col.f32.f16.f16.f32 "
        "{%0,%1,%2,%3}, {%4,%5,%6,%7}, {%8,%9}, {%0,%1,%2,%3};"
        : "+f"(d[0]), "+f"(d[1]), "+f"(d[2]), "+f"(d[3])
        : "r"(a[0]), "r"(a[1]), "r"(a[2]), "r"(a[3]), "r"(b0), "r"(b1));
}

// ---------------- kernel 1: conflict-aware scheduling + sincos ----------------
__global__ void __launch_bounds__(NPAIR) sched_kernel(const int* __restrict__ blocks,
                                                      const float* __restrict__ angles) {
    __shared__ int  cnt[32];
    __shared__ int  jflag[8 * 32];
    __shared__ unsigned char taken[NPAIR];
    __shared__ int  sfree[NPAIR];
    __shared__ int  nfree, ovfp;
    const int r = blockIdx.x;
    const int t = threadIdx.x;
    if (t < 32) cnt[t] = 0;
    jflag[t] = 0;
    taken[t] = 0;
    if (t == 0) { nfree = 0; ovfp = 0; }
    __syncthreads();

    const int i = blocks[(r * NPAIR + t) * 2];
    const int j = blocks[(r * NPAIR + t) * 2 + 1];
    float s, c;
    sincosf(angles[r * NPAIR + t], &s, &c);
    const int bi = i & 31, bj = j & 31;

    const int oA = cnt[bi], oB = cnt[bj];
    const int fA = (oA < 8) && (jflag[oA * 32 + bj] == 0);
    const int fB = (oB < 8) && (jflag[oB * 32 + bi] == 0);
    int pref_first;
    if (fA != fB) pref_first = fA;
    else          pref_first = (oA <= oB);

    int slot = -1, swapped = 0;
    const int b0 = pref_first ? bi : bj;
    const int jb0 = pref_first ? bj : bi;
    int occ = atomicAdd(&cnt[b0], 1);
    if (occ < 8) {
        slot = occ * 32 + b0; swapped = pref_first ? 0 : 1;
        jflag[occ * 32 + jb0] = 1;
    } else {
        atomicSub(&cnt[b0], 1);
        const int b1 = pref_first ? bj : bi;
        const int jb1 = pref_first ? bi : bj;
        occ = atomicAdd(&cnt[b1], 1);
        if (occ < 8) {
            slot = occ * 32 + b1; swapped = pref_first ? 1 : 0;
            jflag[occ * 32 + jb1] = 1;
        } else atomicSub(&cnt[b1], 1);
    }
    if (slot >= 0) taken[slot] = 1;
    __syncthreads();
    if (!taken[t]) { int k = atomicAdd(&nfree, 1); sfree[k] = t; }
    __syncthreads();
    if (slot < 0) { int k = atomicAdd(&ovfp, 1); slot = sfree[k]; }

    const uint32_t ii = (uint32_t)(swapped ? j : i);
    const uint32_t jj = (uint32_t)(swapped ? i : j);
    g_sched[r * NPAIR + slot] = ii | (jj << 16);
    g_cs  [r * NPAIR + slot] = make_float2(c, swapped ? -s : s);
}

// ---------------- kernel 2 (fused): build V0 / V1^T via float2 row-pairs + cast x ----------------
// Two U-rows packed per float2 smem word: same rotation (c,s) applies to both halves.
// Blocks [0,64):    seg0 rounds [0,256)   -> g_V0h   (8 rows each)
// Blocks [64,128):  seg1 rounds [256,511) -> g_V1Th  (transposed)
// Blocks [128,384): cast x -> fp16.
__global__ void __launch_bounds__(256) build_split_kernel(const float4* __restrict__ x4) {
    const int t = threadIdx.x;
    if (blockIdx.x < 128) {
        __shared__ float2 rowp[NPAIRROWS][N_DIM];           // 16 KB
        const int seg   = blockIdx.x >> 6;                  // 0 or 1
        const int obase = (blockIdx.x & 63) * (2 * NPAIRROWS);
        const int r0 = seg ? SEG0_END : 0;
        const int r1 = seg ? NROUND   : SEG0_END;
        #pragma unroll
        for (int p = 0; p < NPAIRROWS; p++) {
            #pragma unroll
            for (int h = 0; h < 2; h++) {
                const int c = t + h * 256;
                float2 v;
                v.x = (c == obase + 2 * p)     ? 1.0f : 0.0f;
                v.y = (c == obase + 2 * p + 1) ? 1.0f : 0.0f;
                rowp[p][c] = v;
            }
        }
        uint32_t id = g_sched[r0 * NPAIR + t];
        float2   cs = g_cs[r0 * NPAIR + t];
        __syncthreads();
        for (int r = r0; r < r1; r++) {
            const int nidx = (r + 1 < r1) ? (r + 1) * NPAIR + t : r0 * NPAIR + t;
            const uint32_t id_n = g_sched[nidx];
            const float2   cs_n = g_cs[nidx];
            const int i = (int)(id & 0xFFFFu);
            const int j = (int)(id >> 16);
            #pragma unroll
            for (int p = 0; p < NPAIRROWS; p++) {
                const float2 ui = rowp[p][i];
                const float2 uj = rowp[p][j];
                float2 ni, nj;
                ni.x = fmaf(cs.x, ui.x, cs.y * uj.x);
                ni.y = fmaf(cs.x, ui.y, cs.y * uj.y);
                nj.x = fmaf(cs.x, uj.x, -(cs.y * ui.x));
                nj.y = fmaf(cs.x, uj.y, -(cs.y * ui.y));
                rowp[p][i] = ni;
                rowp[p][j] = nj;
            }
            __syncthreads();
            id = id_n; cs = cs_n;
        }
        if (seg == 0) {
            // V0 rows, K-major fp16: row obase+2p+h, column c
            #pragma unroll
            for (int p = 0; p < NPAIRROWS; p++)
                for (int c = t; c < N_DIM; c += 256) {
                    const float2 v = rowp[p][c];
                    g_V0h[(obase + 2 * p)     * N_DIM + c] = __float2half(v.x);
                    g_V0h[(obase + 2 * p + 1) * N_DIM + c] = __float2half(v.y);
                }
        } else {
            // V1 transposed: g_V1Th[c*512 + obase+2p+{0,1}] = rowp[p][c].{x,y}
            #pragma unroll
            for (int c = t; c < N_DIM; c += 256) {
                #pragma unroll
                for (int p = 0; p < NPAIRROWS; p++) {
                    const float2 v = rowp[p][c];
                    __half2 hp;
                    hp.x = __float2half(v.x);
                    hp.y = __float2half(v.y);
                    *(__half2*)&g_V1Th[c * N_DIM + obase + 2 * p] = hp;
                }
            }
        }
    } else {
        // cast x -> fp16
        const int bs = blockIdx.x - 128;                    // 0..255
        const int base = bs * 8192;                         // 256*8192 = 2^21 float4 exact
        #pragma unroll 4
        for (int k = 0; k < 32; k++) {
            const int idx = base + k * 256 + t;
            const float4 v = x4[idx];
            __half2 a, b;
            a.x = __float2half(v.x); a.y = __float2half(v.y);
            b.x = __float2half(v.z); b.y = __float2half(v.w);
            ((__half2*)g_xh)[2 * idx]     = a;
            ((__half2*)g_xh)[2 * idx + 1] = b;
        }
    }
}

// ---------------- shared HMMA tile machinery: CTA tile 64(M) x 128(N), 128 thr ----------------
#define KC        64
#define PITCH     144
#define ATILE_SB  (64 * PITCH)              // 9216 B
#define BTILE_SB  (128 * PITCH)             // 18432 B
#define STAGE_SB  (ATILE_SB + BTILE_SB)     // 27648 B
#define NSTAGE    2
#define GEMM_SMEM (NSTAGE * STAGE_SB)       // 55296 B
#define NCHUNK    8

__device__ __forceinline__ void issue_chunk_gen(uint32_t sbase, int i, int m0, int n0, int tid,
                                                const __half* __restrict__ Abuf,
                                                const __half* __restrict__ Bbuf) {
    if (i < NCHUNK) {
        const __half* gA = Abuf + (size_t)m0 * N_DIM + i * KC;
        const __half* gB = Bbuf + (size_t)n0 * N_DIM + i * KC;
        const uint32_t stage = sbase + (uint32_t)(i & 1) * STAGE_SB;
        #pragma unroll
        for (int tt = 0; tt < 4; tt++) {                    // A: 64 rows -> 512 x 16B
            const int idx = tid + tt * 128;
            const int row = idx >> 3, seg = idx & 7;
            cp_async16(stage + (uint32_t)(row * PITCH + seg * 16),
                       gA + (size_t)row * N_DIM + seg * 8);
        }
        #pragma unroll
        for (int tt = 0; tt < 8; tt++) {                    // B: 128 rows -> 1024 x 16B
            const int idx = tid + tt * 128;
            const int row = idx >> 3, seg = idx & 7;
            cp_async16(stage + ATILE_SB + (uint32_t)(row * PITCH + seg * 16),
                       gB + (size_t)row * N_DIM + seg * 8);
        }
    }
    asm volatile("cp.async.commit_group;" ::: "memory");
}

__device__ __forceinline__ void hmma_tile(uint32_t sb, int m0, int n0, int tid,
                                          const __half* __restrict__ Abuf,
                                          const __half* __restrict__ Bbuf,
                                          float acc[2][8][4]) {
    const int lane  = tid & 31;
    const int wid   = tid >> 5;
    const int warpM = wid & 1;
    const int warpN = wid >> 1;
    const int lrow = lane & 15;
    const int loct = lane >> 4;

    issue_chunk_gen(sb, 0, m0, n0, tid, Abuf, Bbuf);
    issue_chunk_gen(sb, 1, m0, n0, tid, Abuf, Bbuf);

    for (int i = 0; i < NCHUNK; i++) {
        asm volatile("cp.async.wait_group 1;" ::: "memory");
        __syncthreads();

        const uint32_t stage = sb + (uint32_t)(i & 1) * STAGE_SB;
        const uint32_t sA = stage + (uint32_t)((warpM * 32 + lrow) * PITCH);
        const uint32_t sB = stage + ATILE_SB + (uint32_t)((warpN * 64 + lrow) * PITCH);

        #pragma unroll
        for (int ks = 0; ks < 4; ks++) {
            const uint32_t koff = (uint32_t)(ks * 32 + loct * 16);
            uint32_t afr[2][4], bfr[4][4];
            #pragma unroll
            for (int mi = 0; mi < 2; mi++)
                ldm_x4(afr[mi], sA + (uint32_t)(mi * 16 * PITCH) + koff);
            #pragma unroll
            for (int nj = 0; nj < 4; nj++)
                ldm_x4(bfr[nj], sB + (uint32_t)(nj * 16 * PITCH) + koff);
            #pragma unroll
            for (int mi = 0; mi < 2; mi++)
                #pragma unroll
                for (int t = 0; t < 8; t++) {
                    const int nj = t >> 1, hl = t & 1;
                    mma16816(acc[mi][t], afr[mi], bfr[nj][hl], bfr[nj][hl + 2]);
                }
        }
        __syncthreads();
        issue_chunk_gen(sb, i + 2, m0, n0, tid, Abuf, Bbuf);
    }
}

// ---------------- kernel 3: fixup  U = V0 * V1  via HMMA (32 CTAs) ----------------
__global__ void __launch_bounds__(128, 4) fixup_kernel() {
    extern __shared__ char smem[];
    const uint32_t sb = smem_u32(smem);
    const int tid = threadIdx.x;
    const int lane = tid & 31;
    const int wid  = tid >> 5;
    const int n0 = blockIdx.x * 128;
    const int m0 = blockIdx.y * 64;

    float acc[2][8][4];
    #pragma unroll
    for (int a = 0; a < 2; a++)
        #pragma unroll
        for (int b = 0; b < 8; b++)
            #pragma unroll
            for (int c = 0; c < 4; c++) acc[a][b][c] = 0.0f;

    hmma_tile(sb, m0, n0, tid, g_V0h, g_V1Th, acc);

    const int warpM = wid & 1;
    const int warpN = wid >> 1;
    const int rbase = m0 + warpM * 32 + (lane >> 2);
    const int cbase = n0 + warpN * 64 + (lane & 3) * 2;
    #pragma unroll
    for (int t = 0; t < 8; t++) {
        const int col = cbase + t * 8;
        #pragma unroll
        for (int mi = 0; mi < 2; mi++) {
            const int r0 = rbase + mi * 16;
            __half2 h0, h1;
            h0.x = __float2half(acc[mi][t][0]); h0.y = __float2half(acc[mi][t][1]);
            h1.x = __float2half(acc[mi][t][2]); h1.y = __float2half(acc[mi][t][3]);
            *(__half2*)&g_Uh[(size_t)r0 * N_DIM + col]       = h0;
            *(__half2*)&g_Uh[(size_t)(r0 + 8) * N_DIM + col] = h1;
        }
    }
}

// ---------------- kernel 4: main fp16 GEMM out = x @ U^T + bias (1024 CTAs) ----------------
__global__ void __launch_bounds__(128, 4) gemm_kernel(float* __restrict__ out,
                                                      const float* __restrict__ bias) {
    extern __shared__ char smem[];
    const uint32_t sb = smem_u32(smem);
    const int tid = threadIdx.x;
    const int lane = tid & 31;
    const int wid  = tid >> 5;
    const int n0 = blockIdx.x * 128;
    const int m0 = blockIdx.y * 64;

    float acc[2][8][4];
    #pragma unroll
    for (int a = 0; a < 2; a++)
        #pragma unroll
        for (int b = 0; b < 8; b++)
            #pragma unroll
            for (int c = 0; c < 4; c++) acc[a][b][c] = 0.0f;

    hmma_tile(sb, m0, n0, tid, g_xh, g_Uh, acc);

    const int warpM = wid & 1;
    const int warpN = wid >> 1;
    const int rbase = m0 + warpM * 32 + (lane >> 2);
    const int cbase = n0 + warpN * 64 + (lane & 3) * 2;
    #pragma unroll
    for (int t = 0; t < 8; t++) {
        const int col = cbase + t * 8;
        const float2 bv = __ldg((const float2*)&bias[col]);
        #pragma unroll
        for (int mi = 0; mi < 2; mi++) {
            const int r0 = rbase + mi * 16;
            float2 v0, v1;
            v0.x = acc[mi][t][0] + bv.x; v0.y = acc[mi][t][1] + bv.y;
            v1.x = acc[mi][t][2] + bv.x; v1.y = acc[mi][t][3] + bv.y;
            *(float2*)&out[(size_t)r0 * N_DIM + col]       = v0;
            *(float2*)&out[(size_t)(r0 + 8) * N_DIM + col] = v1;
        }
    }
}

// ---------------- launch ----------------
extern "C" void kernel_launch(void* const* d_in, const int* in_sizes, int n_in,
                              void* d_out, int out_size) {
    const float* x = nullptr;
    const float* angles = nullptr;
    const float* bias = nullptr;
    const int*   blocks = nullptr;
    for (int i = 0; i < n_in; i++) {
        const long sz = in_sizes[i];
        if      (sz == (long)BATCH_DIM * N_DIM)  x      = (const float*)d_in[i];
        else if (sz == (long)NROUND * NPAIR)     angles = (const float*)d_in[i];
        else if (sz == (long)N_DIM)              bias   = (const float*)d_in[i];
        else if (sz == (long)NROUND * NPAIR * 2) blocks = (const int*)d_in[i];
    }
    float* out = (float*)d_out;

    sched_kernel<<<NROUND, NPAIR>>>(blocks, angles);
    build_split_kernel<<<384, 256>>>((const float4*)x);
    cudaFuncSetAttribute(fixup_kernel, cudaFuncAttributeMaxDynamicSharedMemorySize, GEMM_SMEM);
    fixup_kernel<<<dim3(4, 8), 128, GEMM_SMEM>>>();
    cudaFuncSetAttribute(gemm_kernel, cudaFuncAttributeMaxDynamicSharedMemorySize, GEMM_SMEM);
    gemm_kernel<<<dim3(4, 256), 128, GEMM_SMEM>>>(out, bias);
}